// round 1
// baseline (speedup 1.0000x reference)
#include <cuda_runtime.h>
#include <cstdint>

#define NNODES 100000
#define DIM    128

// ---------------- scratch (static __device__, no runtime alloc) ----------------
__device__ float g_ln[NNODES * DIM];   // normalized x (no affine)
__device__ float g_A [NNODES * DIM];   // sum_{u->v} ln[u]  indexed by v (forward agg)
__device__ float g_Ar[NNODES * DIM];   // sum_{u->v} ln[v]  indexed by u (reverse agg)
__device__ float g_din [NNODES];       // in-degree  (float)
__device__ float g_dout[NNODES];       // out-degree (float)

// ---------------- helpers ----------------
__device__ __forceinline__ uint32_t f2tf(float f) {
    uint32_t r;
    asm("cvt.rna.tf32.f32 %0, %1;" : "=r"(r) : "f"(f));
    return r;
}

__device__ __forceinline__ void red_add_v4(float* p, float4 v) {
    asm volatile("red.global.add.v4.f32 [%0], {%1, %2, %3, %4};"
                 :: "l"(p), "f"(v.x), "f"(v.y), "f"(v.z), "f"(v.w) : "memory");
}

__device__ __forceinline__ void mma_tf32(float* c, const uint32_t* a, const uint32_t* b) {
    asm volatile(
        "mma.sync.aligned.m16n8k8.row.col.f32.tf32.tf32.f32 "
        "{%0,%1,%2,%3}, {%4,%5,%6,%7}, {%8,%9}, {%0,%1,%2,%3};\n"
        : "+f"(c[0]), "+f"(c[1]), "+f"(c[2]), "+f"(c[3])
        : "r"(a[0]), "r"(a[1]), "r"(a[2]), "r"(a[3]), "r"(b[0]), "r"(b[1]));
}

// ---------------- kernel 0: zero accumulators ----------------
__global__ void zero_kernel(int n_f4, int n_nodes) {
    int i = blockIdx.x * blockDim.x + threadIdx.x;
    float4 z = make_float4(0.f, 0.f, 0.f, 0.f);
    if (i < n_f4) {
        reinterpret_cast<float4*>(g_A)[i]  = z;
        reinterpret_cast<float4*>(g_Ar)[i] = z;
    }
    if (i < n_nodes) { g_din[i] = 0.f; g_dout[i] = 0.f; }
}

// ---------------- kernel 1: layernorm-normalize (no affine), warp per row ----------------
__global__ void ln_kernel(const float* __restrict__ x, int nrows) {
    int warp = (blockIdx.x * blockDim.x + threadIdx.x) >> 5;
    int lane = threadIdx.x & 31;
    if (warp >= nrows) return;
    const float4* x4 = reinterpret_cast<const float4*>(x);
    float4 v = x4[warp * 32 + lane];
    float s = v.x + v.y + v.z + v.w;
    #pragma unroll
    for (int o = 16; o > 0; o >>= 1) s += __shfl_xor_sync(0xffffffffu, s, o);
    float mu = s * (1.0f / 128.0f);
    float4 d = make_float4(v.x - mu, v.y - mu, v.z - mu, v.w - mu);
    float ss = d.x*d.x + d.y*d.y + d.z*d.z + d.w*d.w;
    #pragma unroll
    for (int o = 16; o > 0; o >>= 1) ss += __shfl_xor_sync(0xffffffffu, ss, o);
    float rs = rsqrtf(ss * (1.0f / 128.0f) + 1e-5f);
    float4 o4 = make_float4(d.x*rs, d.y*rs, d.z*rs, d.w*rs);
    reinterpret_cast<float4*>(g_ln)[warp * 32 + lane] = o4;
}

// ---------------- kernel 2: edge scatter, warp per edge ----------------
__global__ void scatter_kernel(const int* __restrict__ src, const int* __restrict__ dst,
                               int n_edges) {
    int e = (blockIdx.x * blockDim.x + threadIdx.x) >> 5;
    int lane = threadIdx.x & 31;
    if (e >= n_edges) return;
    int s = src[e];
    int d = dst[e];
    const float4* ln4 = reinterpret_cast<const float4*>(g_ln);
    // forward: A[d] += ln[s]
    float4 vs = ln4[s * 32 + lane];
    red_add_v4(&g_A[d * DIM + lane * 4], vs);
    // reverse: Ar[s] += ln[d]
    float4 vd = ln4[d * 32 + lane];
    red_add_v4(&g_Ar[s * DIM + lane * 4], vd);
    if (lane == 0) {
        atomicAdd(&g_din[d], 1.0f);
        atomicAdd(&g_dout[s], 1.0f);
    }
}

// ---------------- kernel 3: fused SAGE GEMM (tf32 mma) + epilogue ----------------
// Computes for 128 rows:  z = [xn | hn] @ [Wself | Wneigh]^T  (K = 256)
//   xn[k] = ln[k]*gamma[k]+beta[k]
//   hn[k] = deg>0 ? (agg[k]/deg)*gamma[k]+beta[k] : 0
// out[r] = addsrc[r] + relu(z[r] + bias)
#define SB_STRIDE 260   // 256 + pad; bank = (4n + k) & 31 -> conflict-free B frags
#define SA_STRIDE 36    // 32 + pad;  bank = (4r + k) & 31 -> conflict-free A frags
#define GEMM_SMEM ((128 * SB_STRIDE + 128 * SA_STRIDE) * 4)

__global__ __launch_bounds__(256) void gemm_kernel(
    const float* __restrict__ gamma, const float* __restrict__ beta,
    const float* __restrict__ Wself, const float* __restrict__ Wneigh,
    const float* __restrict__ bias,
    const float* __restrict__ addsrc, float* __restrict__ out,
    int nrows, int dir)
{
    extern __shared__ float smem[];
    float* sB = smem;                   // [n:128][k:256] stride SB_STRIDE
    float* sA = smem + 128 * SB_STRIDE; // [r:128][k:32]  stride SA_STRIDE

    const float* ln  = g_ln;
    const float* agg = dir ? g_Ar   : g_A;
    const float* deg = dir ? g_dout : g_din;

    int tid  = threadIdx.x;
    int lane = tid & 31;
    int warp = tid >> 5;
    int wm = warp >> 1;          // 0..3 -> 32-row slab
    int wn = warp & 1;           // 0..1 -> 64-col slab
    int row0 = blockIdx.x * 128;
    int t = lane & 3, g = lane >> 2;

    // ---- stage weights: sB[n][k] = (k<128 ? Wself : Wneigh)[n][k%128], tf32-rounded ----
    #pragma unroll
    for (int half = 0; half < 2; half++) {
        const float4* W4 = reinterpret_cast<const float4*>(half ? Wneigh : Wself);
        int koff = half * 128;
        #pragma unroll
        for (int j = 0; j < 16; j++) {
            int idx = tid + j * 256;        // 4096 float4 per matrix
            int n = idx >> 5, c4 = idx & 31;
            float4 v = W4[n * 32 + c4];
            float4 o;
            o.x = __uint_as_float(f2tf(v.x));
            o.y = __uint_as_float(f2tf(v.y));
            o.z = __uint_as_float(f2tf(v.z));
            o.w = __uint_as_float(f2tf(v.w));
            *reinterpret_cast<float4*>(sB + n * SB_STRIDE + koff + c4 * 4) = o;
        }
    }

    float acc[2][8][4];
    #pragma unroll
    for (int mi = 0; mi < 2; mi++)
        #pragma unroll
        for (int ni = 0; ni < 8; ni++)
            #pragma unroll
            for (int q = 0; q < 4; q++) acc[mi][ni][q] = 0.f;

    const float4* ga4 = reinterpret_cast<const float4*>(gamma);
    const float4* be4 = reinterpret_cast<const float4*>(beta);

    for (int kc = 0; kc < 256; kc += 32) {
        // ---- build A tile: 128 rows x 32 k ----
        bool isAgg = (kc >= 128);
        #pragma unroll
        for (int j = 0; j < 4; j++) {
            int idx = tid + j * 256;        // 1024 float4
            int row = idx >> 3, c4 = idx & 7;
            int gr = row0 + row;
            float4 v = make_float4(0.f, 0.f, 0.f, 0.f);
            if (gr < nrows) {
                if (!isAgg) {
                    int col4 = (kc >> 2) + c4;
                    float4 xv = reinterpret_cast<const float4*>(ln)[gr * 32 + col4];
                    float4 gm = ga4[col4];
                    float4 bt = be4[col4];
                    v.x = xv.x * gm.x + bt.x;
                    v.y = xv.y * gm.y + bt.y;
                    v.z = xv.z * gm.z + bt.z;
                    v.w = xv.w * gm.w + bt.w;
                } else {
                    int col4 = ((kc - 128) >> 2) + c4;
                    float dg  = deg[gr];
                    float inv = dg > 0.f ? 1.0f / dg : 0.f;
                    float msk = dg > 0.f ? 1.0f : 0.f;
                    float4 av = reinterpret_cast<const float4*>(agg)[gr * 32 + col4];
                    float4 gm = ga4[col4];
                    float4 bt = be4[col4];
                    v.x = av.x * (gm.x * inv) + bt.x * msk;
                    v.y = av.y * (gm.y * inv) + bt.y * msk;
                    v.z = av.z * (gm.z * inv) + bt.z * msk;
                    v.w = av.w * (gm.w * inv) + bt.w * msk;
                }
            }
            float4 o;
            o.x = __uint_as_float(f2tf(v.x));
            o.y = __uint_as_float(f2tf(v.y));
            o.z = __uint_as_float(f2tf(v.z));
            o.w = __uint_as_float(f2tf(v.w));
            *reinterpret_cast<float4*>(sA + row * SA_STRIDE + c4 * 4) = o;
        }
        __syncthreads();

        // ---- 4 x (k=8) mma steps ----
        #pragma unroll
        for (int k8 = 0; k8 < 32; k8 += 8) {
            uint32_t af[2][4];
            #pragma unroll
            for (int mi = 0; mi < 2; mi++) {
                const float* base = sA + (wm * 32 + mi * 16 + g) * SA_STRIDE + k8 + t;
                af[mi][0] = __float_as_uint(base[0]);
                af[mi][1] = __float_as_uint(base[8 * SA_STRIDE]);
                af[mi][2] = __float_as_uint(base[4]);
                af[mi][3] = __float_as_uint(base[8 * SA_STRIDE + 4]);
            }
            uint32_t bf[8][2];
            #pragma unroll
            for (int ni = 0; ni < 8; ni++) {
                const float* base = sB + (wn * 64 + ni * 8 + g) * SB_STRIDE + kc + k8 + t;
                bf[ni][0] = __float_as_uint(base[0]);
                bf[ni][1] = __float_as_uint(base[4]);
            }
            #pragma unroll
            for (int mi = 0; mi < 2; mi++)
                #pragma unroll
                for (int ni = 0; ni < 8; ni++)
                    mma_tf32(acc[mi][ni], af[mi], bf[ni]);
        }
        __syncthreads();
    }

    // ---- epilogue: out = addsrc + relu(acc + bias) ----
    const float2* add2 = reinterpret_cast<const float2*>(addsrc);
    float2*       out2 = reinterpret_cast<float2*>(out);
    const float2* b2   = reinterpret_cast<const float2*>(bias);
    #pragma unroll
    for (int mi = 0; mi < 2; mi++) {
        int r1 = row0 + wm * 32 + mi * 16 + g;
        int r2 = r1 + 8;
        #pragma unroll
        for (int ni = 0; ni < 8; ni++) {
            int col = wn * 64 + ni * 8 + t * 2;
            float2 bv = b2[col >> 1];
            if (r1 < nrows) {
                int e = (r1 * DIM + col) >> 1;
                float2 a = add2[e];
                float2 o;
                o.x = a.x + fmaxf(acc[mi][ni][0] + bv.x, 0.f);
                o.y = a.y + fmaxf(acc[mi][ni][1] + bv.y, 0.f);
                out2[e] = o;
            }
            if (r2 < nrows) {
                int e = (r2 * DIM + col) >> 1;
                float2 a = add2[e];
                float2 o;
                o.x = a.x + fmaxf(acc[mi][ni][2] + bv.x, 0.f);
                o.y = a.y + fmaxf(acc[mi][ni][3] + bv.y, 0.f);
                out2[e] = o;
            }
        }
    }
}

// ---------------- launch ----------------
extern "C" void kernel_launch(void* const* d_in, const int* in_sizes, int n_in,
                              void* d_out, int out_size)
{
    const float* x       = (const float*)d_in[0];
    const int*   src     = (const int*)  d_in[1];
    const int*   dst     = (const int*)  d_in[2];
    const float* gamma   = (const float*)d_in[3];
    const float* beta    = (const float*)d_in[4];
    const float* Wself   = (const float*)d_in[5];
    const float* Wneigh  = (const float*)d_in[6];
    const float* b       = (const float*)d_in[7];
    const float* gamma_r = (const float*)d_in[8];
    const float* beta_r  = (const float*)d_in[9];
    const float* Wself_r = (const float*)d_in[10];
    const float* Wneigh_r= (const float*)d_in[11];
    const float* b_r     = (const float*)d_in[12];
    float* out = (float*)d_out;

    int N = in_sizes[0] / DIM;       // 100000
    int E = in_sizes[1];             // 640000
    int n_f4 = N * (DIM / 4);        // float4 count per accumulator array

    // 0) zero accumulators
    {
        int blocks = (n_f4 + 255) / 256;
        zero_kernel<<<blocks, 256>>>(n_f4, N);
    }
    // 1) normalize
    {
        int blocks = (N + 7) / 8;    // 8 warps/block, warp per row
        ln_kernel<<<blocks, 256>>>(x, N);
    }
    // 2) edge scatter (both directions)
    {
        int blocks = (E + 7) / 8;    // 8 warps/block, warp per edge
        scatter_kernel<<<blocks, 256>>>(src, dst, E);
    }
    // 3) fused GEMMs
    cudaFuncSetAttribute(gemm_kernel, cudaFuncAttributeMaxDynamicSharedMemorySize, GEMM_SMEM);
    int gblocks = (N + 127) / 128;
    // dir 0: out = x + relu(sage_fwd)
    gemm_kernel<<<gblocks, 256, GEMM_SMEM>>>(gamma, beta, Wself, Wneigh, b,
                                             x, out, N, 0);
    // dir 1: out += relu(sage_rev)
    gemm_kernel<<<gblocks, 256, GEMM_SMEM>>>(gamma_r, beta_r, Wself_r, Wneigh_r, b_r,
                                             out, out, N, 1);
}

// round 2
// speedup vs baseline: 1.4304x; 1.4304x over previous
#include <cuda_runtime.h>
#include <cstdint>

#define NNODES 100000
#define DIM    128

// ---------------- scratch (static __device__, no runtime alloc) ----------------
__device__ float g_ln[NNODES * DIM];   // normalized x (no affine)
__device__ float g_A [NNODES * DIM];   // sum_{u->v} ln[u]  indexed by v (forward agg)
__device__ float g_Ar[NNODES * DIM];   // sum_{u->v} ln[v]  indexed by u (reverse agg)
__device__ float g_din [NNODES];       // in-degree  (float)
__device__ float g_dout[NNODES];       // out-degree (float)

// ---------------- helpers ----------------
__device__ __forceinline__ uint32_t f2tf(float f) {
    uint32_t r;
    asm("cvt.rna.tf32.f32 %0, %1;" : "=r"(r) : "f"(f));
    return r;
}

__device__ __forceinline__ void red_add_v4(float* p, float4 v) {
    asm volatile("red.global.add.v4.f32 [%0], {%1, %2, %3, %4};"
                 :: "l"(p), "f"(v.x), "f"(v.y), "f"(v.z), "f"(v.w) : "memory");
}

__device__ __forceinline__ void mma_tf32(float* c, const uint32_t* a, const uint32_t* b) {
    asm volatile(
        "mma.sync.aligned.m16n8k8.row.col.f32.tf32.tf32.f32 "
        "{%0,%1,%2,%3}, {%4,%5,%6,%7}, {%8,%9}, {%0,%1,%2,%3};\n"
        : "+f"(c[0]), "+f"(c[1]), "+f"(c[2]), "+f"(c[3])
        : "r"(a[0]), "r"(a[1]), "r"(a[2]), "r"(a[3]), "r"(b[0]), "r"(b[1]));
}

// ---------------- kernel 0: zero accumulators ----------------
__global__ void zero_kernel(int n_f4, int n_nodes) {
    int i = blockIdx.x * blockDim.x + threadIdx.x;
    float4 z = make_float4(0.f, 0.f, 0.f, 0.f);
    if (i < n_f4) {
        reinterpret_cast<float4*>(g_A)[i]  = z;
        reinterpret_cast<float4*>(g_Ar)[i] = z;
    }
    if (i < n_nodes) { g_din[i] = 0.f; g_dout[i] = 0.f; }
}

// ---------------- kernel 1: layernorm-normalize (no affine), warp per row ----------------
__global__ void ln_kernel(const float* __restrict__ x, int nrows) {
    int warp = (blockIdx.x * blockDim.x + threadIdx.x) >> 5;
    int lane = threadIdx.x & 31;
    if (warp >= nrows) return;
    const float4* x4 = reinterpret_cast<const float4*>(x);
    float4 v = x4[warp * 32 + lane];
    float s = v.x + v.y + v.z + v.w;
    #pragma unroll
    for (int o = 16; o > 0; o >>= 1) s += __shfl_xor_sync(0xffffffffu, s, o);
    float mu = s * (1.0f / 128.0f);
    float4 d = make_float4(v.x - mu, v.y - mu, v.z - mu, v.w - mu);
    float ss = d.x*d.x + d.y*d.y + d.z*d.z + d.w*d.w;
    #pragma unroll
    for (int o = 16; o > 0; o >>= 1) ss += __shfl_xor_sync(0xffffffffu, ss, o);
    float rs = rsqrtf(ss * (1.0f / 128.0f) + 1e-5f);
    float4 o4 = make_float4(d.x*rs, d.y*rs, d.z*rs, d.w*rs);
    reinterpret_cast<float4*>(g_ln)[warp * 32 + lane] = o4;
}

// ---------------- kernel 2: edge scatter, warp per edge ----------------
__global__ void scatter_kernel(const int* __restrict__ src, const int* __restrict__ dst,
                               int n_edges) {
    int e = (blockIdx.x * blockDim.x + threadIdx.x) >> 5;
    int lane = threadIdx.x & 31;
    if (e >= n_edges) return;
    int s = src[e];
    int d = dst[e];
    const float4* ln4 = reinterpret_cast<const float4*>(g_ln);
    float4 vs = ln4[s * 32 + lane];
    red_add_v4(&g_A[d * DIM + lane * 4], vs);
    float4 vd = ln4[d * 32 + lane];
    red_add_v4(&g_Ar[s * DIM + lane * 4], vd);
    if (lane == 0) {
        atomicAdd(&g_din[d], 1.0f);
        atomicAdd(&g_dout[s], 1.0f);
    }
}

// ---------------- kernel 3: persistent fused SAGE GEMM (tf32 mma) ----------------
// Weights staged ONCE per CTA (gamma folded in, beta folded to bias terms).
// A operand = raw [ln | agg] via double-buffered cp.async; 1/deg applied in
// epilogue by linearity with split accumulators.
//   out[r,:] = addsrc[r,:] + relu(accS + inv_deg[r]*accN + (b + Wself@beta)
//                                 + mask[r]*(Wneigh@beta))
#define GTPB      512
#define SB_STRIDE 260   // 256 + 4 pad: bank = (4n + k) & 31 -> conflict-free
#define SA_STRIDE 36    // 32 + 4 pad
#define GEMM_SMEM ((128 * SB_STRIDE + 2 * 128 * SA_STRIDE + 256) * 4)

__global__ __launch_bounds__(GTPB, 1) void gemm_kernel(
    const float* __restrict__ gamma, const float* __restrict__ beta,
    const float* __restrict__ Wself, const float* __restrict__ Wneigh,
    const float* __restrict__ bias,
    const float* __restrict__ addsrc, float* __restrict__ out,
    int nrows, int dir)
{
    extern __shared__ float smem[];
    float* sB    = smem;                        // [n:128][k:256] stride 260
    float* sA0   = sB  + 128 * SB_STRIDE;       // [r:128][k:32]  stride 36
    float* sA1   = sA0 + 128 * SA_STRIDE;
    float* sbias = sA1 + 128 * SA_STRIDE;       // [128]: b + Wself@beta
    float* scn   = sbias + 128;                 // [128]: Wneigh@beta

    const float*  deg  = dir ? g_dout : g_din;
    const float4* ln4  = reinterpret_cast<const float4*>(g_ln);
    const float4* agg4 = reinterpret_cast<const float4*>(dir ? g_Ar : g_A);

    int tid  = threadIdx.x;
    int lane = tid & 31;
    int warp = tid >> 5;
    int wm = warp >> 2;          // 0..3 : 32-row slab
    int wn = warp & 3;           // 0..3 : 32-col slab
    int t = lane & 3, g = lane >> 2;

    // ---- stage weights once: sB[n][k] = W[n][k%128] * gamma[k%128], tf32 ----
    const float4* ga4 = reinterpret_cast<const float4*>(gamma);
    #pragma unroll
    for (int half = 0; half < 2; half++) {
        const float4* W4 = reinterpret_cast<const float4*>(half ? Wneigh : Wself);
        int koff = half * 128;
        #pragma unroll
        for (int j = 0; j < 8; j++) {
            int idx = tid + j * GTPB;           // 4096 float4 per matrix
            int n = idx >> 5, c4 = idx & 31;
            float4 v  = W4[n * 32 + c4];
            float4 gm = ga4[c4];
            float4 o;
            o.x = __uint_as_float(f2tf(v.x * gm.x));
            o.y = __uint_as_float(f2tf(v.y * gm.y));
            o.z = __uint_as_float(f2tf(v.z * gm.z));
            o.w = __uint_as_float(f2tf(v.w * gm.w));
            *reinterpret_cast<float4*>(sB + n * SB_STRIDE + koff + c4 * 4) = o;
        }
    }
    // ---- bias terms: sbias[n] = b[n] + Wself[n,:]@beta ; scn[n] = Wneigh[n,:]@beta ----
    if (tid < 128) {
        const float4* be4 = reinterpret_cast<const float4*>(beta);
        const float4* Ws4 = reinterpret_cast<const float4*>(Wself);
        const float4* Wn4 = reinterpret_cast<const float4*>(Wneigh);
        float cs = 0.f, cn = 0.f;
        #pragma unroll 8
        for (int k4 = 0; k4 < 32; k4++) {
            float4 bv = be4[k4];
            float4 ws = Ws4[tid * 32 + k4];
            float4 wv = Wn4[tid * 32 + k4];
            cs += bv.x*ws.x + bv.y*ws.y + bv.z*ws.z + bv.w*ws.w;
            cn += bv.x*wv.x + bv.y*wv.y + bv.z*wv.z + bv.w*wv.w;
        }
        sbias[tid] = bias[tid] + cs;
        scn[tid]   = cn;
    }
    __syncthreads();

#define ISSUE_CHUNK(KC, DST) do {                                              \
    const float4* srcb = ((KC) < 4) ? ln4 : agg4;                              \
    int c4b = ((KC) & 3) << 3;                                                 \
    _Pragma("unroll")                                                          \
    for (int j = 0; j < 2; j++) {                                              \
        int idx = tid + j * GTPB;                                              \
        int row = idx >> 3, c4 = idx & 7;                                      \
        int gr = row0 + row;                                                   \
        const float4* gp = srcb + (size_t)gr * 32 + c4b + c4;                  \
        uint32_t da = (uint32_t)__cvta_generic_to_shared((DST) + row * SA_STRIDE + c4 * 4); \
        int sz = (gr < nrows) ? 16 : 0;                                        \
        asm volatile("cp.async.cg.shared.global [%0], [%1], 16, %2;"           \
                     :: "r"(da), "l"(gp), "r"(sz));                            \
    }                                                                          \
} while (0)

#define MMA_CHUNK(ACC) do {                                                    \
    _Pragma("unroll")                                                          \
    for (int k8 = 0; k8 < 32; k8 += 8) {                                       \
        uint32_t af[2][4];                                                     \
        _Pragma("unroll")                                                      \
        for (int mi = 0; mi < 2; mi++) {                                       \
            const float* ab = cur + (wm * 32 + mi * 16 + g) * SA_STRIDE + k8 + t; \
            af[mi][0] = __float_as_uint(ab[0]);                                \
            af[mi][1] = __float_as_uint(ab[8 * SA_STRIDE]);                    \
            af[mi][2] = __float_as_uint(ab[4]);                                \
            af[mi][3] = __float_as_uint(ab[8 * SA_STRIDE + 4]);                \
        }                                                                      \
        uint32_t bf[4][2];                                                     \
        _Pragma("unroll")                                                      \
        for (int ni = 0; ni < 4; ni++) {                                       \
            const float* bb = sB + (wn * 32 + ni * 8 + g) * SB_STRIDE + kc * 32 + k8 + t; \
            bf[ni][0] = __float_as_uint(bb[0]);                                \
            bf[ni][1] = __float_as_uint(bb[4]);                                \
        }                                                                      \
        _Pragma("unroll")                                                      \
        for (int mi = 0; mi < 2; mi++)                                         \
            _Pragma("unroll")                                                  \
            for (int ni = 0; ni < 4; ni++)                                     \
                mma_tf32(ACC[mi][ni], af[mi], bf[ni]);                         \
    }                                                                          \
} while (0)

    int ntiles = (nrows + 127) >> 7;
    for (int tile = blockIdx.x; tile < ntiles; tile += gridDim.x) {
        int row0 = tile << 7;

        float accS[2][4][4], accN[2][4][4];
        #pragma unroll
        for (int mi = 0; mi < 2; mi++)
            #pragma unroll
            for (int ni = 0; ni < 4; ni++)
                #pragma unroll
                for (int q = 0; q < 4; q++) { accS[mi][ni][q] = 0.f; accN[mi][ni][q] = 0.f; }

        ISSUE_CHUNK(0, sA0);
        asm volatile("cp.async.commit_group;" ::: "memory");

        #pragma unroll 1
        for (int kc = 0; kc < 8; kc++) {
            float* cur = (kc & 1) ? sA1 : sA0;
            float* nxt = (kc & 1) ? sA0 : sA1;
            if (kc < 7) {
                ISSUE_CHUNK(kc + 1, nxt);
                asm volatile("cp.async.commit_group;" ::: "memory");
                asm volatile("cp.async.wait_group 1;" ::: "memory");
            } else {
                asm volatile("cp.async.wait_group 0;" ::: "memory");
            }
            __syncthreads();
            if (kc < 4) { MMA_CHUNK(accS); } else { MMA_CHUNK(accN); }
            __syncthreads();
        }

        // ---- epilogue ----
        const float2* add2 = reinterpret_cast<const float2*>(addsrc);
        float2*       out2 = reinterpret_cast<float2*>(out);
        #pragma unroll
        for (int mi = 0; mi < 2; mi++) {
            int r1 = row0 + wm * 32 + mi * 16 + g;
            int r2 = r1 + 8;
            float dg1 = (r1 < nrows) ? deg[r1] : 1.f;
            float dg2 = (r2 < nrows) ? deg[r2] : 1.f;
            float inv1 = dg1 > 0.f ? 1.f / dg1 : 0.f;
            float inv2 = dg2 > 0.f ? 1.f / dg2 : 0.f;
            float m1 = dg1 > 0.f ? 1.f : 0.f;
            float m2 = dg2 > 0.f ? 1.f : 0.f;
            #pragma unroll
            for (int ni = 0; ni < 4; ni++) {
                int col = wn * 32 + ni * 8 + t * 2;
                float b0 = sbias[col], b1 = sbias[col + 1];
                float c0 = scn[col],   c1 = scn[col + 1];
                if (r1 < nrows) {
                    int e = (r1 * DIM + col) >> 1;
                    float2 a = add2[e];
                    float v0 = accS[mi][ni][0] + inv1 * accN[mi][ni][0] + b0 + m1 * c0;
                    float v1 = accS[mi][ni][1] + inv1 * accN[mi][ni][1] + b1 + m1 * c1;
                    float2 o; o.x = a.x + fmaxf(v0, 0.f); o.y = a.y + fmaxf(v1, 0.f);
                    out2[e] = o;
                }
                if (r2 < nrows) {
                    int e = (r2 * DIM + col) >> 1;
                    float2 a = add2[e];
                    float v0 = accS[mi][ni][2] + inv2 * accN[mi][ni][2] + b0 + m2 * c0;
                    float v1 = accS[mi][ni][3] + inv2 * accN[mi][ni][3] + b1 + m2 * c1;
                    float2 o; o.x = a.x + fmaxf(v0, 0.f); o.y = a.y + fmaxf(v1, 0.f);
                    out2[e] = o;
                }
            }
        }
    }
#undef ISSUE_CHUNK
#undef MMA_CHUNK
}

// ---------------- launch ----------------
extern "C" void kernel_launch(void* const* d_in, const int* in_sizes, int n_in,
                              void* d_out, int out_size)
{
    const float* x       = (const float*)d_in[0];
    const int*   src     = (const int*)  d_in[1];
    const int*   dst     = (const int*)  d_in[2];
    const float* gamma   = (const float*)d_in[3];
    const float* beta    = (const float*)d_in[4];
    const float* Wself   = (const float*)d_in[5];
    const float* Wneigh  = (const float*)d_in[6];
    const float* b       = (const float*)d_in[7];
    const float* gamma_r = (const float*)d_in[8];
    const float* beta_r  = (const float*)d_in[9];
    const float* Wself_r = (const float*)d_in[10];
    const float* Wneigh_r= (const float*)d_in[11];
    const float* b_r     = (const float*)d_in[12];
    float* out = (float*)d_out;

    int N = in_sizes[0] / DIM;       // 100000
    int E = in_sizes[1];             // 640000
    int n_f4 = N * (DIM / 4);

    {
        int blocks = (n_f4 + 255) / 256;
        zero_kernel<<<blocks, 256>>>(n_f4, N);
    }
    {
        int blocks = (N + 7) / 8;
        ln_kernel<<<blocks, 256>>>(x, N);
    }
    {
        int blocks = (E + 7) / 8;
        scatter_kernel<<<blocks, 256>>>(src, dst, E);
    }
    cudaFuncSetAttribute(gemm_kernel, cudaFuncAttributeMaxDynamicSharedMemorySize, GEMM_SMEM);
    int ntiles = (N + 127) / 128;
    int gblocks = ntiles < 148 ? ntiles : 148;
    gemm_kernel<<<gblocks, GTPB, GEMM_SMEM>>>(gamma, beta, Wself, Wneigh, b,
                                              x, out, N, 0);
    gemm_kernel<<<gblocks, GTPB, GEMM_SMEM>>>(gamma_r, beta_r, Wself_r, Wneigh_r, b_r,
                                              out, out, N, 1);
}

// round 3
// speedup vs baseline: 1.4940x; 1.0444x over previous
#include <cuda_runtime.h>
#include <cstdint>

#define NNODES 100000
#define DIM    128

// ---------------- scratch (static __device__, no runtime alloc) ----------------
__device__ float g_ln[NNODES * DIM];   // normalized x (no affine)
__device__ float g_A [NNODES * DIM];   // mean_{(u->v)} ln[u]  indexed by v (fwd, pre-scaled)
__device__ float g_Ar[NNODES * DIM];   // mean_{(u->v)} ln[v]  indexed by u (rev, pre-scaled)
__device__ float g_din [NNODES];       // in-degree  -> becomes 1/deg (0 if deg==0)
__device__ float g_dout[NNODES];       // out-degree -> becomes 1/deg (0 if deg==0)

// ---------------- helpers ----------------
__device__ __forceinline__ uint32_t f2tf(float f) {
    uint32_t r;
    asm("cvt.rna.tf32.f32 %0, %1;" : "=r"(r) : "f"(f));
    return r;
}

__device__ __forceinline__ void red_add_v4(float* p, float4 v) {
    asm volatile("red.global.add.v4.f32 [%0], {%1, %2, %3, %4};"
                 :: "l"(p), "f"(v.x), "f"(v.y), "f"(v.z), "f"(v.w) : "memory");
}

__device__ __forceinline__ void mma_tf32(float* c, const uint32_t* a, const uint32_t* b) {
    asm volatile(
        "mma.sync.aligned.m16n8k8.row.col.f32.tf32.tf32.f32 "
        "{%0,%1,%2,%3}, {%4,%5,%6,%7}, {%8,%9}, {%0,%1,%2,%3};\n"
        : "+f"(c[0]), "+f"(c[1]), "+f"(c[2]), "+f"(c[3])
        : "r"(a[0]), "r"(a[1]), "r"(a[2]), "r"(a[3]), "r"(b[0]), "r"(b[1]));
}

// ---------------- kernel 1: layernorm-normalize + zero accumulators ----------------
__global__ void ln_kernel(const float* __restrict__ x, int nrows) {
    int warp = (blockIdx.x * blockDim.x + threadIdx.x) >> 5;
    int lane = threadIdx.x & 31;
    if (warp >= nrows) return;
    const float4* x4 = reinterpret_cast<const float4*>(x);
    float4 v = x4[warp * 32 + lane];
    float s = v.x + v.y + v.z + v.w;
    #pragma unroll
    for (int o = 16; o > 0; o >>= 1) s += __shfl_xor_sync(0xffffffffu, s, o);
    float mu = s * (1.0f / 128.0f);
    float4 d = make_float4(v.x - mu, v.y - mu, v.z - mu, v.w - mu);
    float ss = d.x*d.x + d.y*d.y + d.z*d.z + d.w*d.w;
    #pragma unroll
    for (int o = 16; o > 0; o >>= 1) ss += __shfl_xor_sync(0xffffffffu, ss, o);
    float rs = rsqrtf(ss * (1.0f / 128.0f) + 1e-5f);
    float4 o4 = make_float4(d.x*rs, d.y*rs, d.z*rs, d.w*rs);
    reinterpret_cast<float4*>(g_ln)[warp * 32 + lane] = o4;
    float4 z = make_float4(0.f, 0.f, 0.f, 0.f);
    reinterpret_cast<float4*>(g_A )[warp * 32 + lane] = z;
    reinterpret_cast<float4*>(g_Ar)[warp * 32 + lane] = z;
    if (lane == 0) { g_din[warp] = 0.f; g_dout[warp] = 0.f; }
}

// ---------------- kernel 2a: degree count ----------------
__global__ void deg_kernel(const int* __restrict__ src, const int* __restrict__ dst,
                           int n_edges) {
    int e = blockIdx.x * blockDim.x + threadIdx.x;
    if (e >= n_edges) return;
    atomicAdd(&g_din [dst[e]], 1.0f);
    atomicAdd(&g_dout[src[e]], 1.0f);
}

// ---------------- kernel 2b: invert degrees in place ----------------
__global__ void inv_kernel(int n_nodes) {
    int i = blockIdx.x * blockDim.x + threadIdx.x;
    if (i >= n_nodes) return;
    float a = g_din[i];
    float b = g_dout[i];
    g_din[i]  = a > 0.f ? __frcp_rn(a) : 0.f;
    g_dout[i] = b > 0.f ? __frcp_rn(b) : 0.f;
}

// ---------------- kernel 2c: edge scatter (mean directly), warp per edge ----------------
__global__ void scatter_kernel(const int* __restrict__ src, const int* __restrict__ dst,
                               int n_edges) {
    int e = (blockIdx.x * blockDim.x + threadIdx.x) >> 5;
    int lane = threadIdx.x & 31;
    if (e >= n_edges) return;
    int s = src[e];
    int d = dst[e];
    float invd = g_din[d];     // broadcast (same addr across warp)
    float invs = g_dout[s];
    const float4* ln4 = reinterpret_cast<const float4*>(g_ln);
    float4 vs = ln4[s * 32 + lane];
    vs.x *= invd; vs.y *= invd; vs.z *= invd; vs.w *= invd;
    red_add_v4(&g_A[d * DIM + lane * 4], vs);
    float4 vd = ln4[d * 32 + lane];
    vd.x *= invs; vd.y *= invs; vd.z *= invs; vd.w *= invs;
    red_add_v4(&g_Ar[s * DIM + lane * 4], vd);
}

// ---------------- kernel 3: persistent fused SAGE GEMM (tf32 mma) ----------------
// Block tile 256x128, 16 warps, warp tile 32x64 (2 m-blocks x 8 n-blocks).
// Weights staged once (gamma folded), beta folded into bias terms, single acc
// (agg already holds the mean), mask for beta-neigh term in epilogue.
//   out[r,:] = addsrc[r,:] + relu(acc + (b + Wself@beta) + mask[r]*(Wneigh@beta))
#define GTPB      512
#define MTILE     256
#define SB_STRIDE 260   // 256 + 4 pad: bank = (4n + k) & 31 -> conflict-free
#define SA_STRIDE 36    // 32 + 4 pad
#define GEMM_SMEM ((128 * SB_STRIDE + 2 * MTILE * SA_STRIDE + 256) * 4)

__global__ __launch_bounds__(GTPB, 1) void gemm_kernel(
    const float* __restrict__ gamma, const float* __restrict__ beta,
    const float* __restrict__ Wself, const float* __restrict__ Wneigh,
    const float* __restrict__ bias,
    const float* __restrict__ addsrc, float* __restrict__ out,
    int nrows, int dir)
{
    extern __shared__ float smem[];
    float* sB    = smem;                          // [n:128][k:256] stride 260
    float* sA0   = sB  + 128 * SB_STRIDE;         // [r:256][k:32]  stride 36
    float* sA1   = sA0 + MTILE * SA_STRIDE;
    float* sbias = sA1 + MTILE * SA_STRIDE;       // [128]: b + Wself@beta
    float* scn   = sbias + 128;                   // [128]: Wneigh@beta

    const float*  deg  = dir ? g_dout : g_din;    // holds inv (0 iff deg==0)
    const float4* ln4  = reinterpret_cast<const float4*>(g_ln);
    const float4* agg4 = reinterpret_cast<const float4*>(dir ? g_Ar : g_A);

    int tid  = threadIdx.x;
    int lane = tid & 31;
    int warp = tid >> 5;
    int wm = warp >> 1;          // 0..7 : 32-row slab
    int wn = warp & 1;           // 0..1 : 64-col slab
    int t = lane & 3, g = lane >> 2;

    // ---- stage weights once: sB[n][k] = W[n][k%128] * gamma[k%128], tf32 ----
    const float4* ga4 = reinterpret_cast<const float4*>(gamma);
    #pragma unroll
    for (int half = 0; half < 2; half++) {
        const float4* W4 = reinterpret_cast<const float4*>(half ? Wneigh : Wself);
        int koff = half * 128;
        #pragma unroll
        for (int j = 0; j < 8; j++) {
            int idx = tid + j * GTPB;           // 4096 float4 per matrix
            int n = idx >> 5, c4 = idx & 31;
            float4 v  = W4[n * 32 + c4];
            float4 gm = ga4[c4];
            float4 o;
            o.x = __uint_as_float(f2tf(v.x * gm.x));
            o.y = __uint_as_float(f2tf(v.y * gm.y));
            o.z = __uint_as_float(f2tf(v.z * gm.z));
            o.w = __uint_as_float(f2tf(v.w * gm.w));
            *reinterpret_cast<float4*>(sB + n * SB_STRIDE + koff + c4 * 4) = o;
        }
    }
    // ---- bias terms ----
    if (tid < 128) {
        const float4* be4 = reinterpret_cast<const float4*>(beta);
        const float4* Ws4 = reinterpret_cast<const float4*>(Wself);
        const float4* Wn4 = reinterpret_cast<const float4*>(Wneigh);
        float cs = 0.f, cn = 0.f;
        #pragma unroll 8
        for (int k4 = 0; k4 < 32; k4++) {
            float4 bv = be4[k4];
            float4 ws = Ws4[tid * 32 + k4];
            float4 wv = Wn4[tid * 32 + k4];
            cs += bv.x*ws.x + bv.y*ws.y + bv.z*ws.z + bv.w*ws.w;
            cn += bv.x*wv.x + bv.y*wv.y + bv.z*wv.z + bv.w*wv.w;
        }
        sbias[tid] = bias[tid] + cs;
        scn[tid]   = cn;
    }
    __syncthreads();

#define ISSUE_CHUNK(KC, DST) do {                                              \
    const float4* srcb = ((KC) < 4) ? ln4 : agg4;                              \
    int c4b = ((KC) & 3) << 3;                                                 \
    _Pragma("unroll")                                                          \
    for (int j = 0; j < 4; j++) {                                              \
        int idx = tid + j * GTPB;                                              \
        int row = idx >> 3, c4 = idx & 7;                                      \
        int gr = row0 + row;                                                   \
        const float4* gp = srcb + (size_t)gr * 32 + c4b + c4;                  \
        uint32_t da = (uint32_t)__cvta_generic_to_shared((DST) + row * SA_STRIDE + c4 * 4); \
        int sz = (gr < nrows) ? 16 : 0;                                        \
        asm volatile("cp.async.cg.shared.global [%0], [%1], 16, %2;"           \
                     :: "r"(da), "l"(gp), "r"(sz));                            \
    }                                                                          \
} while (0)

#define MMA_CHUNK() do {                                                       \
    _Pragma("unroll")                                                          \
    for (int k8 = 0; k8 < 32; k8 += 8) {                                       \
        uint32_t af[2][4];                                                     \
        _Pragma("unroll")                                                      \
        for (int mi = 0; mi < 2; mi++) {                                       \
            const float* ab = cur + (wm * 32 + mi * 16 + g) * SA_STRIDE + k8 + t; \
            af[mi][0] = __float_as_uint(ab[0]);                                \
            af[mi][1] = __float_as_uint(ab[8 * SA_STRIDE]);                    \
            af[mi][2] = __float_as_uint(ab[4]);                                \
            af[mi][3] = __float_as_uint(ab[8 * SA_STRIDE + 4]);                \
        }                                                                      \
        uint32_t bf[8][2];                                                     \
        _Pragma("unroll")                                                      \
        for (int ni = 0; ni < 8; ni++) {                                       \
            const float* bb = sB + (wn * 64 + ni * 8 + g) * SB_STRIDE + kc * 32 + k8 + t; \
            bf[ni][0] = __float_as_uint(bb[0]);                                \
            bf[ni][1] = __float_as_uint(bb[4]);                                \
        }                                                                      \
        _Pragma("unroll")                                                      \
        for (int mi = 0; mi < 2; mi++)                                         \
            _Pragma("unroll")                                                  \
            for (int ni = 0; ni < 8; ni++)                                     \
                mma_tf32(acc[mi][ni], af[mi], bf[ni]);                         \
    }                                                                          \
} while (0)

    int ntiles = (nrows + MTILE - 1) / MTILE;
    for (int tile = blockIdx.x; tile < ntiles; tile += gridDim.x) {
        int row0 = tile * MTILE;

        float acc[2][8][4];
        #pragma unroll
        for (int mi = 0; mi < 2; mi++)
            #pragma unroll
            for (int ni = 0; ni < 8; ni++)
                #pragma unroll
                for (int q = 0; q < 4; q++) acc[mi][ni][q] = 0.f;

        ISSUE_CHUNK(0, sA0);
        asm volatile("cp.async.commit_group;" ::: "memory");

        #pragma unroll 1
        for (int kc = 0; kc < 8; kc++) {
            float* cur = (kc & 1) ? sA1 : sA0;
            float* nxt = (kc & 1) ? sA0 : sA1;
            if (kc < 7) {
                ISSUE_CHUNK(kc + 1, nxt);
                asm volatile("cp.async.commit_group;" ::: "memory");
                asm volatile("cp.async.wait_group 1;" ::: "memory");
            } else {
                asm volatile("cp.async.wait_group 0;" ::: "memory");
            }
            __syncthreads();
            MMA_CHUNK();
            __syncthreads();
        }

        // ---- epilogue ----
        const float2* add2 = reinterpret_cast<const float2*>(addsrc);
        float2*       out2 = reinterpret_cast<float2*>(out);
        #pragma unroll
        for (int mi = 0; mi < 2; mi++) {
            int r1 = row0 + wm * 32 + mi * 16 + g;
            int r2 = r1 + 8;
            float m1 = (r1 < nrows && deg[r1] > 0.f) ? 1.f : 0.f;
            float m2 = (r2 < nrows && deg[r2] > 0.f) ? 1.f : 0.f;
            #pragma unroll
            for (int ni = 0; ni < 8; ni++) {
                int col = wn * 64 + ni * 8 + t * 2;
                float b0 = sbias[col], b1 = sbias[col + 1];
                float c0 = scn[col],   c1 = scn[col + 1];
                if (r1 < nrows) {
                    int e = (r1 * DIM + col) >> 1;
                    float2 a = add2[e];
                    float v0 = acc[mi][ni][0] + b0 + m1 * c0;
                    float v1 = acc[mi][ni][1] + b1 + m1 * c1;
                    float2 o; o.x = a.x + fmaxf(v0, 0.f); o.y = a.y + fmaxf(v1, 0.f);
                    out2[e] = o;
                }
                if (r2 < nrows) {
                    int e = (r2 * DIM + col) >> 1;
                    float2 a = add2[e];
                    float v0 = acc[mi][ni][2] + b0 + m2 * c0;
                    float v1 = acc[mi][ni][3] + b1 + m2 * c1;
                    float2 o; o.x = a.x + fmaxf(v0, 0.f); o.y = a.y + fmaxf(v1, 0.f);
                    out2[e] = o;
                }
            }
        }
    }
#undef ISSUE_CHUNK
#undef MMA_CHUNK
}

// ---------------- launch ----------------
extern "C" void kernel_launch(void* const* d_in, const int* in_sizes, int n_in,
                              void* d_out, int out_size)
{
    const float* x       = (const float*)d_in[0];
    const int*   src     = (const int*)  d_in[1];
    const int*   dst     = (const int*)  d_in[2];
    const float* gamma   = (const float*)d_in[3];
    const float* beta    = (const float*)d_in[4];
    const float* Wself   = (const float*)d_in[5];
    const float* Wneigh  = (const float*)d_in[6];
    const float* b       = (const float*)d_in[7];
    const float* gamma_r = (const float*)d_in[8];
    const float* beta_r  = (const float*)d_in[9];
    const float* Wself_r = (const float*)d_in[10];
    const float* Wneigh_r= (const float*)d_in[11];
    const float* b_r     = (const float*)d_in[12];
    float* out = (float*)d_out;

    int N = in_sizes[0] / DIM;       // 100000
    int E = in_sizes[1];             // 640000

    // 1) normalize + zero accumulators/degrees
    {
        int blocks = (N + 7) / 8;
        ln_kernel<<<blocks, 256>>>(x, N);
    }
    // 2a) degree count
    deg_kernel<<<(E + 255) / 256, 256>>>(src, dst, E);
    // 2b) invert in place
    inv_kernel<<<(N + 255) / 256, 256>>>(N);
    // 2c) edge scatter (mean directly)
    {
        int blocks = (E + 7) / 8;
        scatter_kernel<<<blocks, 256>>>(src, dst, E);
    }
    // 3) fused GEMMs
    cudaFuncSetAttribute(gemm_kernel, cudaFuncAttributeMaxDynamicSharedMemorySize, GEMM_SMEM);
    int ntiles = (N + MTILE - 1) / MTILE;
    int gblocks = ntiles < 148 ? ntiles : 148;
    gemm_kernel<<<gblocks, GTPB, GEMM_SMEM>>>(gamma, beta, Wself, Wneigh, b,
                                              x, out, N, 0);
    gemm_kernel<<<gblocks, GTPB, GEMM_SMEM>>>(gamma_r, beta_r, Wself_r, Wneigh_r, b_r,
                                              out, out, N, 1);
}

// round 4
// speedup vs baseline: 2.3994x; 1.6060x over previous
#include <cuda_runtime.h>
#include <cuda_fp16.h>
#include <cstdint>

#define NNODES 100000
#define DIM    128

// ---------------- scratch (static __device__, no runtime alloc) ----------------
__device__ __half g_lnH[NNODES * DIM];  // normalized x (no affine), fp16
__device__ __half g_AH [NNODES * DIM];  // mean_{(u->v)} ln[u] @ v (fwd, pre-scaled), fp16
__device__ __half g_ArH[NNODES * DIM];  // mean_{(u->v)} ln[v] @ u (rev, pre-scaled), fp16
__device__ float  g_din [NNODES];       // in-degree  -> 1/deg (0 if deg==0)
__device__ float  g_dout[NNODES];       // out-degree -> 1/deg (0 if deg==0)

// ---------------- helpers ----------------
__device__ __forceinline__ void mma_f16(float* c, const uint32_t* a, const uint32_t* b) {
    asm volatile(
        "mma.sync.aligned.m16n8k16.row.col.f32.f16.f16.f32 "
        "{%0,%1,%2,%3}, {%4,%5,%6,%7}, {%8,%9}, {%0,%1,%2,%3};\n"
        : "+f"(c[0]), "+f"(c[1]), "+f"(c[2]), "+f"(c[3])
        : "r"(a[0]), "r"(a[1]), "r"(a[2]), "r"(a[3]), "r"(b[0]), "r"(b[1]));
}

#define LDSM4(R, ADDR) \
    asm volatile("ldmatrix.sync.aligned.m8n8.x4.shared.b16 {%0,%1,%2,%3}, [%4];" \
                 : "=r"((R)[0]), "=r"((R)[1]), "=r"((R)[2]), "=r"((R)[3]) : "r"(ADDR))

__device__ __forceinline__ uint32_t h2u(__half2 h) {
    return *reinterpret_cast<uint32_t*>(&h);
}

// ---------------- kernel 1: layernorm-normalize (fp16 out) + zero accumulators ----------------
__global__ void ln_kernel(const float* __restrict__ x, int nrows) {
    int warp = (blockIdx.x * blockDim.x + threadIdx.x) >> 5;
    int lane = threadIdx.x & 31;
    if (warp >= nrows) return;
    const float4* x4 = reinterpret_cast<const float4*>(x);
    float4 v = x4[warp * 32 + lane];
    float s = v.x + v.y + v.z + v.w;
    #pragma unroll
    for (int o = 16; o > 0; o >>= 1) s += __shfl_xor_sync(0xffffffffu, s, o);
    float mu = s * (1.0f / 128.0f);
    float4 d = make_float4(v.x - mu, v.y - mu, v.z - mu, v.w - mu);
    float ss = d.x*d.x + d.y*d.y + d.z*d.z + d.w*d.w;
    #pragma unroll
    for (int o = 16; o > 0; o >>= 1) ss += __shfl_xor_sync(0xffffffffu, ss, o);
    float rs = rsqrtf(ss * (1.0f / 128.0f) + 1e-5f);
    uint2 o2;
    o2.x = h2u(__floats2half2_rn(d.x * rs, d.y * rs));
    o2.y = h2u(__floats2half2_rn(d.z * rs, d.w * rs));
    reinterpret_cast<uint2*>(g_lnH)[warp * 32 + lane] = o2;
    uint2 z = make_uint2(0u, 0u);
    reinterpret_cast<uint2*>(g_AH )[warp * 32 + lane] = z;
    reinterpret_cast<uint2*>(g_ArH)[warp * 32 + lane] = z;
    if (lane == 0) { g_din[warp] = 0.f; g_dout[warp] = 0.f; }
}

// ---------------- kernel 2a: degree count ----------------
__global__ void deg_kernel(const int* __restrict__ src, const int* __restrict__ dst,
                           int n_edges) {
    int e = blockIdx.x * blockDim.x + threadIdx.x;
    if (e >= n_edges) return;
    atomicAdd(&g_din [dst[e]], 1.0f);
    atomicAdd(&g_dout[src[e]], 1.0f);
}

// ---------------- kernel 2b: invert degrees in place ----------------
__global__ void inv_kernel(int n_nodes) {
    int i = blockIdx.x * blockDim.x + threadIdx.x;
    if (i >= n_nodes) return;
    float a = g_din[i];
    float b = g_dout[i];
    g_din[i]  = a > 0.f ? __frcp_rn(a) : 0.f;
    g_dout[i] = b > 0.f ? __frcp_rn(b) : 0.f;
}

// ---------------- kernel 2c: edge scatter (fp16, both dirs in one warp) ----------------
// lanes 0-15: g_AH[d] += ln[s]*inv_din[d]   (16B per lane)
// lanes 16-31: g_ArH[s] += ln[d]*inv_dout[s]
__global__ void scatter_kernel(const int* __restrict__ src, const int* __restrict__ dst,
                               int n_edges) {
    int e = (blockIdx.x * blockDim.x + threadIdx.x) >> 5;
    int lane = threadIdx.x & 31;
    if (e >= n_edges) return;
    int s = src[e];
    int d = dst[e];
    int rev = lane >> 4;            // 0 fwd, 1 rev
    int c   = lane & 15;            // 16B chunk index within the 256B row
    int nld = rev ? d : s;          // node to read ln from
    int nst = rev ? s : d;          // node accumulator to update
    float inv = rev ? g_dout[s] : g_din[d];     // warp-group broadcast
    __half2 sc = __float2half2_rn(inv);

    uint4 v = reinterpret_cast<const uint4*>(g_lnH)[nld * 16 + c];
    __half2* h = reinterpret_cast<__half2*>(&v);
    h[0] = __hmul2(h[0], sc);
    h[1] = __hmul2(h[1], sc);
    h[2] = __hmul2(h[2], sc);
    h[3] = __hmul2(h[3], sc);

    __half* base = rev ? g_ArH : g_AH;
    __half* p = base + nst * DIM + c * 8;
    asm volatile("red.global.add.noftz.v4.f16x2 [%0], {%1,%2,%3,%4};"
                 :: "l"(p), "r"(v.x), "r"(v.y), "r"(v.z), "r"(v.w) : "memory");
}

// ---------------- kernel 3: persistent fused SAGE GEMM (fp16 mma, fp32 acc) ----------------
// Block tile 256x128, 16 warps, warp tile 32x64. K=256 = [ln | agg] (agg holds mean).
// Weights (gamma folded) staged in fp16 smem once; beta folded to bias terms.
//   out[r,:] = addsrc[r,:] + relu(acc + (b + Wself@beta) + mask[r]*(Wneigh@beta))
#define GTPB   512
#define MTILE  256
#define SB_H   264            // halves: 256 + 8 pad (conflict-free B loads)
#define SA_H   40             // halves: 32 + 8 pad  (conflict-free ldmatrix)
#define SB_BYTES (128 * SB_H * 2)             // 67584
#define SA_BYTES (MTILE * SA_H * 2)           // 20480
#define GEMM_SMEM (SB_BYTES + 2 * SA_BYTES + 256 * 4)

__global__ __launch_bounds__(GTPB, 1) void gemm_kernel(
    const float* __restrict__ gamma, const float* __restrict__ beta,
    const float* __restrict__ Wself, const float* __restrict__ Wneigh,
    const float* __restrict__ bias,
    const float* __restrict__ addsrc, float* __restrict__ out,
    int nrows, int dir)
{
    extern __shared__ char smem[];
    __half* sBh   = reinterpret_cast<__half*>(smem);
    __half* sA0h  = reinterpret_cast<__half*>(smem + SB_BYTES);
    __half* sA1h  = reinterpret_cast<__half*>(smem + SB_BYTES + SA_BYTES);
    float*  sbias = reinterpret_cast<float*>(smem + SB_BYTES + 2 * SA_BYTES);
    float*  scn   = sbias + 128;

    const float* deg  = dir ? g_dout : g_din;   // holds inv (0 iff deg==0)
    const uint4* lnv  = reinterpret_cast<const uint4*>(g_lnH);
    const uint4* aggv = reinterpret_cast<const uint4*>(dir ? g_ArH : g_AH);

    int tid  = threadIdx.x;
    int lane = tid & 31;
    int warp = tid >> 5;
    int wm = warp >> 1;          // 0..7 : 32-row slab
    int wn = warp & 1;           // 0..1 : 64-col slab
    int t = lane & 3, g = lane >> 2;

    uint32_t sA0u = (uint32_t)__cvta_generic_to_shared(sA0h);
    uint32_t sA1u = (uint32_t)__cvta_generic_to_shared(sA1h);

    // ---- stage weights once: sB[n][k] = half(W[n][k%128] * gamma[k%128]) ----
    const float4* ga4 = reinterpret_cast<const float4*>(gamma);
    #pragma unroll
    for (int half = 0; half < 2; half++) {
        const float4* W4 = reinterpret_cast<const float4*>(half ? Wneigh : Wself);
        int koff = half * 128;
        #pragma unroll
        for (int j = 0; j < 8; j++) {
            int idx = tid + j * GTPB;           // 4096 float4 per matrix
            int n = idx >> 5, c4 = idx & 31;
            float4 v  = W4[n * 32 + c4];
            float4 gm = ga4[c4];
            uint2 o;
            o.x = h2u(__floats2half2_rn(v.x * gm.x, v.y * gm.y));
            o.y = h2u(__floats2half2_rn(v.z * gm.z, v.w * gm.w));
            *reinterpret_cast<uint2*>(sBh + n * SB_H + koff + c4 * 4) = o;
        }
    }
    // ---- bias terms (fp32) ----
    if (tid < 128) {
        const float4* be4 = reinterpret_cast<const float4*>(beta);
        const float4* Ws4 = reinterpret_cast<const float4*>(Wself);
        const float4* Wn4 = reinterpret_cast<const float4*>(Wneigh);
        float cs = 0.f, cn = 0.f;
        #pragma unroll 8
        for (int k4 = 0; k4 < 32; k4++) {
            float4 bv = be4[k4];
            float4 ws = Ws4[tid * 32 + k4];
            float4 wv = Wn4[tid * 32 + k4];
            cs += bv.x*ws.x + bv.y*ws.y + bv.z*ws.z + bv.w*ws.w;
            cn += bv.x*wv.x + bv.y*wv.y + bv.z*wv.z + bv.w*wv.w;
        }
        sbias[tid] = bias[tid] + cs;
        scn[tid]   = cn;
    }
    __syncthreads();

// chunk KC (0..7): 32 k-halves; 0-3 from ln, 4-7 from agg. Row = 64B -> 4 x 16B cp.async
#define ISSUE_CHUNK(KC, DSTU) do {                                             \
    const uint4* srcb = ((KC) < 4) ? lnv : aggv;                               \
    int c16 = ((KC) & 3) * 4;                                                  \
    _Pragma("unroll")                                                          \
    for (int j = 0; j < 2; j++) {                                              \
        int idx = tid + j * GTPB;                                              \
        int row = idx >> 2, c8 = idx & 3;                                      \
        int gr = row0 + row;                                                   \
        const uint4* gp = srcb + (size_t)gr * 16 + c16 + c8;                   \
        uint32_t da = (DSTU) + row * (SA_H * 2) + c8 * 16;                     \
        int sz = (gr < nrows) ? 16 : 0;                                        \
        asm volatile("cp.async.cg.shared.global [%0], [%1], 16, %2;"           \
                     :: "r"(da), "l"(gp), "r"(sz));                            \
    }                                                                          \
} while (0)

#define MMA_CHUNK(CURU) do {                                                   \
    _Pragma("unroll")                                                          \
    for (int ks = 0; ks < 2; ks++) {                                           \
        uint32_t af[2][4];                                                     \
        _Pragma("unroll")                                                      \
        for (int mi = 0; mi < 2; mi++) {                                       \
            uint32_t ad = (CURU) +                                             \
                ((wm * 32 + mi * 16 + (lane & 15)) * SA_H + ks * 16 + (lane >> 4) * 8) * 2; \
            LDSM4(af[mi], ad);                                                 \
        }                                                                      \
        uint32_t bf[8][2];                                                     \
        _Pragma("unroll")                                                      \
        for (int ni = 0; ni < 8; ni++) {                                       \
            const __half* bb = sBh + (wn * 64 + ni * 8 + g) * SB_H + kc * 32 + ks * 16 + 2 * t; \
            bf[ni][0] = *reinterpret_cast<const uint32_t*>(bb);                \
            bf[ni][1] = *reinterpret_cast<const uint32_t*>(bb + 8);            \
        }                                                                      \
        _Pragma("unroll")                                                      \
        for (int mi = 0; mi < 2; mi++)                                         \
            _Pragma("unroll")                                                  \
            for (int ni = 0; ni < 8; ni++)                                     \
                mma_f16(acc[mi][ni], af[mi], bf[ni]);                          \
    }                                                                          \
} while (0)

    int ntiles = (nrows + MTILE - 1) / MTILE;
    for (int tile = blockIdx.x; tile < ntiles; tile += gridDim.x) {
        int row0 = tile * MTILE;

        float acc[2][8][4];
        #pragma unroll
        for (int mi = 0; mi < 2; mi++)
            #pragma unroll
            for (int ni = 0; ni < 8; ni++)
                #pragma unroll
                for (int q = 0; q < 4; q++) acc[mi][ni][q] = 0.f;

        ISSUE_CHUNK(0, sA0u);
        asm volatile("cp.async.commit_group;" ::: "memory");

        #pragma unroll 1
        for (int kc = 0; kc < 8; kc++) {
            uint32_t curu = (kc & 1) ? sA1u : sA0u;
            uint32_t nxtu = (kc & 1) ? sA0u : sA1u;
            if (kc < 7) {
                ISSUE_CHUNK(kc + 1, nxtu);
                asm volatile("cp.async.commit_group;" ::: "memory");
                asm volatile("cp.async.wait_group 1;" ::: "memory");
            } else {
                asm volatile("cp.async.wait_group 0;" ::: "memory");
            }
            __syncthreads();
            MMA_CHUNK(curu);
            __syncthreads();
        }

        // ---- epilogue ----
        const float2* add2 = reinterpret_cast<const float2*>(addsrc);
        float2*       out2 = reinterpret_cast<float2*>(out);
        #pragma unroll
        for (int mi = 0; mi < 2; mi++) {
            int r1 = row0 + wm * 32 + mi * 16 + g;
            int r2 = r1 + 8;
            float m1 = (r1 < nrows && deg[r1] > 0.f) ? 1.f : 0.f;
            float m2 = (r2 < nrows && deg[r2] > 0.f) ? 1.f : 0.f;
            #pragma unroll
            for (int ni = 0; ni < 8; ni++) {
                int col = wn * 64 + ni * 8 + t * 2;
                float b0 = sbias[col], b1 = sbias[col + 1];
                float c0 = scn[col],   c1 = scn[col + 1];
                if (r1 < nrows) {
                    int e = (r1 * DIM + col) >> 1;
                    float2 a = add2[e];
                    float v0 = acc[mi][ni][0] + b0 + m1 * c0;
                    float v1 = acc[mi][ni][1] + b1 + m1 * c1;
                    float2 o; o.x = a.x + fmaxf(v0, 0.f); o.y = a.y + fmaxf(v1, 0.f);
                    out2[e] = o;
                }
                if (r2 < nrows) {
                    int e = (r2 * DIM + col) >> 1;
                    float2 a = add2[e];
                    float v0 = acc[mi][ni][2] + b0 + m2 * c0;
                    float v1 = acc[mi][ni][3] + b1 + m2 * c1;
                    float2 o; o.x = a.x + fmaxf(v0, 0.f); o.y = a.y + fmaxf(v1, 0.f);
                    out2[e] = o;
                }
            }
        }
    }
#undef ISSUE_CHUNK
#undef MMA_CHUNK
}

// ---------------- launch ----------------
extern "C" void kernel_launch(void* const* d_in, const int* in_sizes, int n_in,
                              void* d_out, int out_size)
{
    const float* x       = (const float*)d_in[0];
    const int*   src     = (const int*)  d_in[1];
    const int*   dst     = (const int*)  d_in[2];
    const float* gamma   = (const float*)d_in[3];
    const float* beta    = (const float*)d_in[4];
    const float* Wself   = (const float*)d_in[5];
    const float* Wneigh  = (const float*)d_in[6];
    const float* b       = (const float*)d_in[7];
    const float* gamma_r = (const float*)d_in[8];
    const float* beta_r  = (const float*)d_in[9];
    const float* Wself_r = (const float*)d_in[10];
    const float* Wneigh_r= (const float*)d_in[11];
    const float* b_r     = (const float*)d_in[12];
    float* out = (float*)d_out;

    int N = in_sizes[0] / DIM;       // 100000
    int E = in_sizes[1];             // 640000

    // 1) normalize (fp16) + zero accumulators/degrees
    ln_kernel<<<(N + 7) / 8, 256>>>(x, N);
    // 2a) degree count
    deg_kernel<<<(E + 255) / 256, 256>>>(src, dst, E);
    // 2b) invert in place
    inv_kernel<<<(N + 255) / 256, 256>>>(N);
    // 2c) edge scatter (both directions, fp16 vector red)
    scatter_kernel<<<(E + 7) / 8, 256>>>(src, dst, E);
    // 3) fused GEMMs
    cudaFuncSetAttribute(gemm_kernel, cudaFuncAttributeMaxDynamicSharedMemorySize, GEMM_SMEM);
    int ntiles = (N + MTILE - 1) / MTILE;
    int gblocks = ntiles < 148 ? ntiles : 148;
    gemm_kernel<<<gblocks, GTPB, GEMM_SMEM>>>(gamma, beta, Wself, Wneigh, b,
                                              x, out, N, 0);
    gemm_kernel<<<gblocks, GTPB, GEMM_SMEM>>>(gamma_r, beta_r, Wself_r, Wneigh_r, b_r,
                                              out, out, N, 1);
}

// round 7
// speedup vs baseline: 2.4008x; 1.0006x over previous
#include <cuda_runtime.h>
#include <cuda_fp16.h>
#include <cstdint>

#define NNODES 100000
#define DIM    128

// ---------------- scratch (static __device__, no runtime alloc) ----------------
__device__ __half g_lnH[NNODES * DIM];  // normalized x (no affine), fp16
__device__ __half g_AH [NNODES * DIM];  // mean_{(u->v)} ln[u] @ v (fwd, pre-scaled), fp16
__device__ __half g_ArH[NNODES * DIM];  // mean_{(u->v)} ln[v] @ u (rev, pre-scaled), fp16
__device__ float  g_din [NNODES];       // in-degree  -> 1/deg (0 if deg==0)
__device__ float  g_dout[NNODES];       // out-degree -> 1/deg (0 if deg==0)

// ---------------- helpers ----------------
__device__ __forceinline__ void mma_f16(float* c, const uint32_t* a, const uint32_t* b) {
    asm volatile(
        "mma.sync.aligned.m16n8k16.row.col.f32.f16.f16.f32 "
        "{%0,%1,%2,%3}, {%4,%5,%6,%7}, {%8,%9}, {%0,%1,%2,%3};\n"
        : "+f"(c[0]), "+f"(c[1]), "+f"(c[2]), "+f"(c[3])
        : "r"(a[0]), "r"(a[1]), "r"(a[2]), "r"(a[3]), "r"(b[0]), "r"(b[1]));
}

#define LDSM4(R, ADDR) \
    asm volatile("ldmatrix.sync.aligned.m8n8.x4.shared.b16 {%0,%1,%2,%3}, [%4];" \
                 : "=r"((R)[0]), "=r"((R)[1]), "=r"((R)[2]), "=r"((R)[3]) : "r"(ADDR))

__device__ __forceinline__ uint32_t h2u(__half2 h) {
    return *reinterpret_cast<uint32_t*>(&h);
}

// ---------------- kernel 1: layernorm-normalize (fp16 out) + zero accumulators ----------------
__global__ void ln_kernel(const float* __restrict__ x, int nrows) {
    int warp = (blockIdx.x * blockDim.x + threadIdx.x) >> 5;
    int lane = threadIdx.x & 31;
    if (warp >= nrows) return;
    const float4* x4 = reinterpret_cast<const float4*>(x);
    float4 v = x4[warp * 32 + lane];
    float s = v.x + v.y + v.z + v.w;
    #pragma unroll
    for (int o = 16; o > 0; o >>= 1) s += __shfl_xor_sync(0xffffffffu, s, o);
    float mu = s * (1.0f / 128.0f);
    float4 d = make_float4(v.x - mu, v.y - mu, v.z - mu, v.w - mu);
    float ss = d.x*d.x + d.y*d.y + d.z*d.z + d.w*d.w;
    #pragma unroll
    for (int o = 16; o > 0; o >>= 1) ss += __shfl_xor_sync(0xffffffffu, ss, o);
    float rs = rsqrtf(ss * (1.0f / 128.0f) + 1e-5f);
    uint2 o2;
    o2.x = h2u(__floats2half2_rn(d.x * rs, d.y * rs));
    o2.y = h2u(__floats2half2_rn(d.z * rs, d.w * rs));
    reinterpret_cast<uint2*>(g_lnH)[warp * 32 + lane] = o2;
    uint2 z = make_uint2(0u, 0u);
    reinterpret_cast<uint2*>(g_AH )[warp * 32 + lane] = z;
    reinterpret_cast<uint2*>(g_ArH)[warp * 32 + lane] = z;
    if (lane == 0) { g_din[warp] = 0.f; g_dout[warp] = 0.f; }
}

// ---------------- kernel 2a: degree count ----------------
__global__ void deg_kernel(const int* __restrict__ src, const int* __restrict__ dst,
                           int n_edges) {
    int e = blockIdx.x * blockDim.x + threadIdx.x;
    if (e >= n_edges) return;
    atomicAdd(&g_din [dst[e]], 1.0f);
    atomicAdd(&g_dout[src[e]], 1.0f);
}

// ---------------- kernel 2b: invert degrees in place ----------------
__global__ void inv_kernel(int n_nodes) {
    int i = blockIdx.x * blockDim.x + threadIdx.x;
    if (i >= n_nodes) return;
    float a = g_din[i];
    float b = g_dout[i];
    g_din[i]  = a > 0.f ? __frcp_rn(a) : 0.f;
    g_dout[i] = b > 0.f ? __frcp_rn(b) : 0.f;
}

// ---------------- kernel 2c: edge scatter (fp16, both dirs in one warp) ----------------
// lanes 0-15: g_AH[d] += ln[s]*inv_din[d]   (16B per lane)
// lanes 16-31: g_ArH[s] += ln[d]*inv_dout[s]
__global__ void scatter_kernel(const int* __restrict__ src, const int* __restrict__ dst,
                               int n_edges) {
    int e = (blockIdx.x * blockDim.x + threadIdx.x) >> 5;
    int lane = threadIdx.x & 31;
    if (e >= n_edges) return;
    int s = src[e];
    int d = dst[e];
    int rev = lane >> 4;            // 0 fwd, 1 rev
    int c   = lane & 15;            // 16B chunk index within the 256B row
    int nld = rev ? d : s;          // node to read ln from
    int nst = rev ? s : d;          // node accumulator to update
    float inv = rev ? g_dout[s] : g_din[d];     // warp-group broadcast
    __half2 sc = __float2half2_rn(inv);

    uint4 v = reinterpret_cast<const uint4*>(g_lnH)[nld * 16 + c];
    __half2* h = reinterpret_cast<__half2*>(&v);
    h[0] = __hmul2(h[0], sc);
    h[1] = __hmul2(h[1], sc);
    h[2] = __hmul2(h[2], sc);
    h[3] = __hmul2(h[3], sc);

    __half* base = rev ? g_ArH : g_AH;
    __half* p = base + nst * DIM + c * 8;
    asm volatile("red.global.add.noftz.v4.f16x2 [%0], {%1,%2,%3,%4};"
                 :: "l"(p), "r"(v.x), "r"(v.y), "r"(v.z), "r"(v.w) : "memory");
}

// ---------------- kernel 3: persistent fused SAGE GEMM (fp16 mma, fp32 acc) ----------------
// Block tile 256x128, 16 warps, warp tile 32x64. K=256 = [ln | agg] (agg holds mean).
// Weights (gamma folded) staged in fp16 smem once; beta folded to bias terms.
//   out[r,:] = addsrc[r,:] + relu(acc + (b + Wself@beta) + mask[r]*(Wneigh@beta))
#define GTPB   512
#define MTILE  256
#define SB_H   264            // halves: 256 + 8 pad (conflict-free B loads)
#define SA_H   40             // halves: 32 + 8 pad  (conflict-free ldmatrix)
#define SB_BYTES (128 * SB_H * 2)             // 67584
#define SA_BYTES (MTILE * SA_H * 2)           // 20480
#define GEMM_SMEM (SB_BYTES + 2 * SA_BYTES + 256 * 4)

__global__ __launch_bounds__(GTPB, 1) void gemm_kernel(
    const float* __restrict__ gamma, const float* __restrict__ beta,
    const float* __restrict__ Wself, const float* __restrict__ Wneigh,
    const float* __restrict__ bias,
    const float* __restrict__ addsrc, float* __restrict__ out,
    int nrows, int dir)
{
    extern __shared__ char smem[];
    __half* sBh   = reinterpret_cast<__half*>(smem);
    __half* sA0h  = reinterpret_cast<__half*>(smem + SB_BYTES);
    __half* sA1h  = reinterpret_cast<__half*>(smem + SB_BYTES + SA_BYTES);
    float*  sbias = reinterpret_cast<float*>(smem + SB_BYTES + 2 * SA_BYTES);
    float*  scn   = sbias + 128;

    const float* deg  = dir ? g_dout : g_din;   // holds inv (0 iff deg==0)
    const uint4* lnv  = reinterpret_cast<const uint4*>(g_lnH);
    const uint4* aggv = reinterpret_cast<const uint4*>(dir ? g_ArH : g_AH);

    int tid  = threadIdx.x;
    int lane = tid & 31;
    int warp = tid >> 5;
    int wm = warp >> 1;          // 0..7 : 32-row slab
    int wn = warp & 1;           // 0..1 : 64-col slab
    int t = lane & 3, g = lane >> 2;

    uint32_t sA0u = (uint32_t)__cvta_generic_to_shared(sA0h);
    uint32_t sA1u = (uint32_t)__cvta_generic_to_shared(sA1h);

    // ---- stage weights once: sB[n][k] = half(W[n][k%128] * gamma[k%128]) ----
    const float4* ga4 = reinterpret_cast<const float4*>(gamma);
    #pragma unroll
    for (int half = 0; half < 2; half++) {
        const float4* W4 = reinterpret_cast<const float4*>(half ? Wneigh : Wself);
        int koff = half * 128;
        #pragma unroll
        for (int j = 0; j < 8; j++) {
            int idx = tid + j * GTPB;           // 4096 float4 per matrix
            int n = idx >> 5, c4 = idx & 31;
            float4 v  = W4[n * 32 + c4];
            float4 gm = ga4[c4];
            uint2 o;
            o.x = h2u(__floats2half2_rn(v.x * gm.x, v.y * gm.y));
            o.y = h2u(__floats2half2_rn(v.z * gm.z, v.w * gm.w));
            *reinterpret_cast<uint2*>(sBh + n * SB_H + koff + c4 * 4) = o;
        }
    }
    // ---- bias terms (fp32) ----
    if (tid < 128) {
        const float4* be4 = reinterpret_cast<const float4*>(beta);
        const float4* Ws4 = reinterpret_cast<const float4*>(Wself);
        const float4* Wn4 = reinterpret_cast<const float4*>(Wneigh);
        float cs = 0.f, cn = 0.f;
        #pragma unroll 8
        for (int k4 = 0; k4 < 32; k4++) {
            float4 bv = be4[k4];
            float4 ws = Ws4[tid * 32 + k4];
            float4 wv = Wn4[tid * 32 + k4];
            cs += bv.x*ws.x + bv.y*ws.y + bv.z*ws.z + bv.w*ws.w;
            cn += bv.x*wv.x + bv.y*wv.y + bv.z*wv.z + bv.w*wv.w;
        }
        sbias[tid] = bias[tid] + cs;
        scn[tid]   = cn;
    }
    __syncthreads();

// chunk KC (0..7): 32 k-halves; 0-3 from ln, 4-7 from agg. Row = 64B -> 4 x 16B cp.async
#define ISSUE_CHUNK(KC, DSTU) do {                                             \
    const uint4* srcb = ((KC) < 4) ? lnv : aggv;                               \
    int c16 = ((KC) & 3) * 4;                                                  \
    _Pragma("unroll")                                                          \
    for (int j = 0; j < 2; j++) {                                              \
        int idx = tid + j * GTPB;                                              \
        int row = idx >> 2, c8 = idx & 3;                                      \
        int gr = row0 + row;                                                   \
        const uint4* gp = srcb + (size_t)gr * 16 + c16 + c8;                   \
        uint32_t da = (DSTU) + row * (SA_H * 2) + c8 * 16;                     \
        int sz = (gr < nrows) ? 16 : 0;                                        \
        asm volatile("cp.async.cg.shared.global [%0], [%1], 16, %2;"           \
                     :: "r"(da), "l"(gp), "r"(sz));                            \
    }                                                                          \
} while (0)

#define MMA_CHUNK(CURU) do {                                                   \
    _Pragma("unroll")                                                          \
    for (int ks = 0; ks < 2; ks++) {                                           \
        uint32_t af[2][4];                                                     \
        _Pragma("unroll")                                                      \
        for (int mi = 0; mi < 2; mi++) {                                       \
            uint32_t ad = (CURU) +                                             \
                ((wm * 32 + mi * 16 + (lane & 15)) * SA_H + ks * 16 + (lane >> 4) * 8) * 2; \
            LDSM4(af[mi], ad);                                                 \
        }                                                                      \
        uint32_t bf[8][2];                                                     \
        _Pragma("unroll")                                                      \
        for (int ni = 0; ni < 8; ni++) {                                       \
            const __half* bb = sBh + (wn * 64 + ni * 8 + g) * SB_H + kc * 32 + ks * 16 + 2 * t; \
            bf[ni][0] = *reinterpret_cast<const uint32_t*>(bb);                \
            bf[ni][1] = *reinterpret_cast<const uint32_t*>(bb + 8);            \
        }                                                                      \
        _Pragma("unroll")                                                      \
        for (int mi = 0; mi < 2; mi++)                                         \
            _Pragma("unroll")                                                  \
            for (int ni = 0; ni < 8; ni++)                                     \
                mma_f16(acc[mi][ni], af[mi], bf[ni]);                          \
    }                                                                          \
} while (0)

    int ntiles = (nrows + MTILE - 1) / MTILE;
    for (int tile = blockIdx.x; tile < ntiles; tile += gridDim.x) {
        int row0 = tile * MTILE;

        float acc[2][8][4];
        #pragma unroll
        for (int mi = 0; mi < 2; mi++)
            #pragma unroll
            for (int ni = 0; ni < 8; ni++)
                #pragma unroll
                for (int q = 0; q < 4; q++) acc[mi][ni][q] = 0.f;

        ISSUE_CHUNK(0, sA0u);
        asm volatile("cp.async.commit_group;" ::: "memory");

        #pragma unroll 1
        for (int kc = 0; kc < 8; kc++) {
            uint32_t curu = (kc & 1) ? sA1u : sA0u;
            uint32_t nxtu = (kc & 1) ? sA0u : sA1u;
            if (kc < 7) {
                ISSUE_CHUNK(kc + 1, nxtu);
                asm volatile("cp.async.commit_group;" ::: "memory");
                asm volatile("cp.async.wait_group 1;" ::: "memory");
            } else {
                asm volatile("cp.async.wait_group 0;" ::: "memory");
            }
            __syncthreads();
            MMA_CHUNK(curu);
            __syncthreads();
        }

        // ---- epilogue ----
        const float2* add2 = reinterpret_cast<const float2*>(addsrc);
        float2*       out2 = reinterpret_cast<float2*>(out);
        #pragma unroll
        for (int mi = 0; mi < 2; mi++) {
            int r1 = row0 + wm * 32 + mi * 16 + g;
            int r2 = r1 + 8;
            float m1 = (r1 < nrows && deg[r1] > 0.f) ? 1.f : 0.f;
            float m2 = (r2 < nrows && deg[r2] > 0.f) ? 1.f : 0.f;
            #pragma unroll
            for (int ni = 0; ni < 8; ni++) {
                int col = wn * 64 + ni * 8 + t * 2;
                float b0 = sbias[col], b1 = sbias[col + 1];
                float c0 = scn[col],   c1 = scn[col + 1];
                if (r1 < nrows) {
                    int e = (r1 * DIM + col) >> 1;
                    float2 a = add2[e];
                    float v0 = acc[mi][ni][0] + b0 + m1 * c0;
                    float v1 = acc[mi][ni][1] + b1 + m1 * c1;
                    float2 o; o.x = a.x + fmaxf(v0, 0.f); o.y = a.y + fmaxf(v1, 0.f);
                    out2[e] = o;
                }
                if (r2 < nrows) {
                    int e = (r2 * DIM + col) >> 1;
                    float2 a = add2[e];
                    float v0 = acc[mi][ni][2] + b0 + m2 * c0;
                    float v1 = acc[mi][ni][3] + b1 + m2 * c1;
                    float2 o; o.x = a.x + fmaxf(v0, 0.f); o.y = a.y + fmaxf(v1, 0.f);
                    out2[e] = o;
                }
            }
        }
    }
#undef ISSUE_CHUNK
#undef MMA_CHUNK
}

// ---------------- launch ----------------
extern "C" void kernel_launch(void* const* d_in, const int* in_sizes, int n_in,
                              void* d_out, int out_size)
{
    const float* x       = (const float*)d_in[0];
    const int*   src     = (const int*)  d_in[1];
    const int*   dst     = (const int*)  d_in[2];
    const float* gamma   = (const float*)d_in[3];
    const float* beta    = (const float*)d_in[4];
    const float* Wself   = (const float*)d_in[5];
    const float* Wneigh  = (const float*)d_in[6];
    const float* b       = (const float*)d_in[7];
    const float* gamma_r = (const float*)d_in[8];
    const float* beta_r  = (const float*)d_in[9];
    const float* Wself_r = (const float*)d_in[10];
    const float* Wneigh_r= (const float*)d_in[11];
    const float* b_r     = (const float*)d_in[12];
    float* out = (float*)d_out;

    int N = in_sizes[0] / DIM;       // 100000
    int E = in_sizes[1];             // 640000

    // 1) normalize (fp16) + zero accumulators/degrees
    ln_kernel<<<(N + 7) / 8, 256>>>(x, N);
    // 2a) degree count
    deg_kernel<<<(E + 255) / 256, 256>>>(src, dst, E);
    // 2b) invert in place
    inv_kernel<<<(N + 255) / 256, 256>>>(N);
    // 2c) edge scatter (both directions, fp16 vector red)
    scatter_kernel<<<(E + 7) / 8, 256>>>(src, dst, E);
    // 3) fused GEMMs
    cudaFuncSetAttribute(gemm_kernel, cudaFuncAttributeMaxDynamicSharedMemorySize, GEMM_SMEM);
    int ntiles = (N + MTILE - 1) / MTILE;
    int gblocks = ntiles < 148 ? ntiles : 148;
    gemm_kernel<<<gblocks, GTPB, GEMM_SMEM>>>(gamma, beta, Wself, Wneigh, b,
                                              x, out, N, 0);
    gemm_kernel<<<gblocks, GTPB, GEMM_SMEM>>>(gamma_r, beta_r, Wself_r, Wneigh_r, b_r,
                                              out, out, N, 1);
}